// round 1
// baseline (speedup 1.0000x reference)
#include <cuda_runtime.h>
#include <math.h>

#define Bb 4
#define Tt 2048
#define Ff 512
#define Dd 128
#define BT (Bb*Tt)          // 8192
#define Lc 128              // chunk length
#define CC 16               // chunks per batch
#define NC (Bb*CC)          // 64 total chunks

#define CLAMP_V 1e20f
#define EPS_LN 1e-5f
#define EPS_DEN 1e-5f

// ---------------- scratch (device globals; no allocation allowed) ----------
__device__ float g_xn[BT*Ff];        // normalized input      16 MB
__device__ float g_Kb[BT*Dd];        // K = phi(x Wk)          4 MB
__device__ float g_Qb[BT*Dd];        // Q = phi(x Wq)          4 MB
__device__ float g_Vb[BT*Dd];        // V = x Wv               4 MB
__device__ float g_sh[BT*Dd];        // shortcut x sc_w + b    4 MB
__device__ float g_KVc[NC*Dd*Dd];    // per-chunk KV sums      4 MB
__device__ float g_Pex[NC*Dd*Dd];    // exclusive prefixes (+S0) 4 MB
__device__ float g_Kc[NC*Dd];        // per-chunk K sums
__device__ float g_Zex[NC*Dd];       // exclusive Z prefixes (+Z0)
__device__ float g_o0[BT*Dd];        // num/den                4 MB

__device__ __forceinline__ float clipf(float x){
    return fminf(fmaxf(x, -CLAMP_V), CLAMP_V);
}

// ---------------- K_ln : LayerNorm over feature dim -----------------------
__global__ void k_ln(const float* __restrict__ hist,
                     const float* __restrict__ lng,
                     const float* __restrict__ lnb){
    int row = blockIdx.x;             // 0..BT-1
    int tid = threadIdx.x;            // 128 threads, 4 floats each
    const float4* hp = (const float4*)(hist + (size_t)row*Ff);
    float4 v = hp[tid];
    float s  = v.x+v.y+v.z+v.w;
    float sq = v.x*v.x+v.y*v.y+v.z*v.z+v.w*v.w;
    #pragma unroll
    for (int o=16;o;o>>=1){
        s  += __shfl_down_sync(0xffffffffu, s,  o);
        sq += __shfl_down_sync(0xffffffffu, sq, o);
    }
    __shared__ float ss[4], sqs[4];
    if ((tid&31)==0){ ss[tid>>5]=s; sqs[tid>>5]=sq; }
    __syncthreads();
    s  = ss[0]+ss[1]+ss[2]+ss[3];
    sq = sqs[0]+sqs[1]+sqs[2]+sqs[3];
    float mu  = s*(1.0f/Ff);
    float var = sq*(1.0f/Ff) - mu*mu;
    float inv = rsqrtf(var + EPS_LN);
    float4 g4 = ((const float4*)lng)[tid];
    float4 b4 = ((const float4*)lnb)[tid];
    float4 o;
    o.x = (v.x-mu)*inv*g4.x + b4.x;
    o.y = (v.y-mu)*inv*g4.y + b4.y;
    o.z = (v.z-mu)*inv*g4.z + b4.z;
    o.w = (v.w-mu)*inv*g4.w + b4.w;
    ((float4*)(g_xn + (size_t)row*Ff))[tid] = o;
}

// ---------------- shared tile loaders (256-thread blocks) -----------------
// A tile: rows 128 x cols 32, row-major with pad 33 (reads are broadcast)
__device__ __forceinline__ void loadA(float* As, const float* __restrict__ src,
                                      int d0, int stride){
    int tid = threadIdx.x;
    int r = tid/8, c4 = (tid%8)*4;
    #pragma unroll
    for (int rr=0; rr<128; rr+=32){
        float4 v = *(const float4*)&src[(size_t)(rr+r)*stride + d0 + c4];
        As[(rr+r)*33 + c4+0] = v.x;
        As[(rr+r)*33 + c4+1] = v.y;
        As[(rr+r)*33 + c4+2] = v.z;
        As[(rr+r)*33 + c4+3] = v.w;
    }
}
// Transposed tile: dst[32][128] <- src rows 128 x cols 32
__device__ __forceinline__ void loadAT(float* dst, const float* __restrict__ src,
                                       int d0, int stride){
    int tid = threadIdx.x;
    int r = tid/8, c4 = (tid%8)*4;
    #pragma unroll
    for (int rr=0; rr<128; rr+=32){
        float4 v = *(const float4*)&src[(size_t)(rr+r)*stride + d0 + c4];
        dst[(c4+0)*128 + rr+r] = v.x;
        dst[(c4+1)*128 + rr+r] = v.y;
        dst[(c4+2)*128 + rr+r] = v.z;
        dst[(c4+3)*128 + rr+r] = v.w;
    }
}
// B tile: rows 32 x cols 128 natural row-major (k-major source)
__device__ __forceinline__ void loadB(float* Bs, const float* __restrict__ src,
                                      int stride){
    int tid = threadIdx.x;
    int r = tid/32, c4 = (tid%32)*4;
    #pragma unroll
    for (int rr=0; rr<32; rr+=8)
        *(float4*)&Bs[(rr+r)*128 + c4] =
            *(const float4*)&src[(size_t)(rr+r)*stride + c4];
}

// ---------------- K_proj : [8192,512]@[512,128] x4 + activations ----------
__global__ __launch_bounds__(256)
void k_proj(const float* __restrict__ Wk, const float* __restrict__ Wq,
            const float* __restrict__ Wv, const float* __restrict__ scw,
            const float* __restrict__ scb){
    __shared__ float As[128*33];
    __shared__ float Bs[32*128];
    int mid = blockIdx.y;    // 0:K 1:Q 2:V 3:short
    int m0  = blockIdx.x * 128;
    const float* Wg = (mid==0)?Wk:(mid==1)?Wq:(mid==2)?Wv:scw;
    float* outp = (mid==0)?g_Kb:(mid==1)?g_Qb:(mid==2)?g_Vb:g_sh;

    int tid = threadIdx.x, tx = tid%16, ty = tid/16;
    float acc[8][8];
    #pragma unroll
    for (int i=0;i<8;i++)
        #pragma unroll
        for (int j=0;j<8;j++) acc[i][j]=0.f;

    for (int k0=0; k0<Ff; k0+=32){
        loadA(As, g_xn + (size_t)m0*Ff, k0, Ff);
        loadB(Bs, Wg + (size_t)k0*Dd, Dd);
        __syncthreads();
        #pragma unroll
        for (int k=0;k<32;k++){
            float a[8], b[8];
            #pragma unroll
            for (int i=0;i<8;i++) a[i] = As[(ty*8+i)*33 + k];
            *(float4*)&b[0] = *(float4*)&Bs[k*128 + tx*8];
            *(float4*)&b[4] = *(float4*)&Bs[k*128 + tx*8 + 4];
            #pragma unroll
            for (int i=0;i<8;i++)
                #pragma unroll
                for (int j=0;j<8;j++)
                    acc[i][j] = fmaf(a[i], b[j], acc[i][j]);
        }
        __syncthreads();
    }
    #pragma unroll
    for (int i=0;i<8;i++){
        int m = m0 + ty*8 + i;
        #pragma unroll
        for (int j=0;j<8;j++){
            int n = tx*8 + j;
            float z = acc[i][j];
            if (mid<=1) z = (z>0.f) ? z+1.f : expf(z);   // phi = elu+1
            if (mid==3) z += __ldg(&scb[n]);
            acc[i][j] = z;
        }
        *(float4*)&outp[(size_t)m*Dd + tx*8]     = *(float4*)&acc[i][0];
        *(float4*)&outp[(size_t)m*Dd + tx*8 + 4] = *(float4*)&acc[i][4];
    }
}

// ---------------- K_chunksum : per-chunk sum of K_t (x) V_t ---------------
__global__ __launch_bounds__(256)
void k_chunksum(){
    __shared__ float Ks[32*128];
    __shared__ float Vs[32*128];
    int bc = blockIdx.x;                 // 0..NC-1
    int tid = threadIdx.x, tx = tid%16, ty = tid/16;
    size_t base = (size_t)bc * Lc * Dd;
    float acc[8][8];
    #pragma unroll
    for (int i=0;i<8;i++)
        #pragma unroll
        for (int j=0;j<8;j++) acc[i][j]=0.f;

    for (int tt=0; tt<Lc; tt+=32){
        loadB(Ks, g_Kb + base + (size_t)tt*Dd, Dd);
        loadB(Vs, g_Vb + base + (size_t)tt*Dd, Dd);
        __syncthreads();
        #pragma unroll
        for (int s=0;s<32;s++){
            float a[8], b[8];
            #pragma unroll
            for (int i=0;i<8;i++) a[i] = Ks[s*128 + ty*8 + i];
            *(float4*)&b[0] = *(float4*)&Vs[s*128 + tx*8];
            *(float4*)&b[4] = *(float4*)&Vs[s*128 + tx*8 + 4];
            #pragma unroll
            for (int i=0;i<8;i++)
                #pragma unroll
                for (int j=0;j<8;j++)
                    acc[i][j] = fmaf(a[i], b[j], acc[i][j]);
        }
        __syncthreads();
    }
    size_t ob = (size_t)bc*Dd*Dd;
    #pragma unroll
    for (int i=0;i<8;i++){
        *(float4*)&g_KVc[ob + (size_t)(ty*8+i)*Dd + tx*8]     = *(float4*)&acc[i][0];
        *(float4*)&g_KVc[ob + (size_t)(ty*8+i)*Dd + tx*8 + 4] = *(float4*)&acc[i][4];
    }
}

// ---------------- K_kc : per-chunk sums of K ------------------------------
__global__ void k_kc(){
    int bc = blockIdx.x; int d = threadIdx.x;
    size_t base = (size_t)bc * Lc * Dd + d;
    float a0=0,a1=0,a2=0,a3=0;
    for (int t=0;t<Lc;t+=4){
        a0 += g_Kb[base + (size_t)(t  )*Dd];
        a1 += g_Kb[base + (size_t)(t+1)*Dd];
        a2 += g_Kb[base + (size_t)(t+2)*Dd];
        a3 += g_Kb[base + (size_t)(t+3)*Dd];
    }
    g_Kc[bc*Dd + d] = (a0+a1)+(a2+a3);
}

// ---------------- K_prefix : exclusive prefix of KV chunk sums (+S0) ------
__global__ void k_prefix(const float* __restrict__ S0){
    int i = blockIdx.x, b = blockIdx.y, j = threadIdx.x;
    float r = S0[((size_t)b*Dd + i)*Dd + j];
    for (int c=0;c<CC;c++){
        size_t idx = ((size_t)(b*CC+c)*Dd + i)*Dd + j;
        g_Pex[idx] = r;
        r += g_KVc[idx];
    }
}

// ---------------- K_zex : exclusive prefix of K chunk sums (+Z0) ----------
__global__ void k_zex(const float* __restrict__ Z0){
    int b = blockIdx.x, d = threadIdx.x;
    float r = Z0[b*Dd + d];
    for (int c=0;c<CC;c++){
        g_Zex[(b*CC+c)*Dd + d] = r;
        r += g_Kc[(b*CC+c)*Dd + d];
    }
}

// ---------------- K_scan : intra-chunk scan, streams S (and Z) out --------
__global__ __launch_bounds__(128)
void k_scan(float* __restrict__ Sout, float* __restrict__ Zout){
    int g = blockIdx.x;   // 8 groups of 16 i-rows
    int c = blockIdx.y;   // chunk
    int b = blockIdx.z;   // batch
    int tid = threadIdx.x;
    int js = tid & 31;          // 32 column groups of 4
    int isub = tid >> 5;        // warp id -> 4 i-subgroups of 4
    int ib = g*16 + isub*4;
    int bc = b*CC + c;
    size_t tokbase = (size_t)bc * Lc;     // global token of chunk start

    __shared__ float sk[128*16];
    for (int idx = tid; idx < 128*16; idx += 128){
        int t_ = idx >> 4, i_ = idx & 15;
        sk[idx] = g_Kb[(tokbase + t_)*Dd + g*16 + i_];
    }

    float4 R[4];
    size_t pbase = (size_t)bc*Dd*Dd;
    #pragma unroll
    for (int a=0;a<4;a++)
        R[a] = *(const float4*)&g_Pex[pbase + (size_t)(ib+a)*Dd + js*4];

    bool doZ = (g==0 && isub==0);
    float4 zr = make_float4(0,0,0,0);
    if (doZ) zr = *(const float4*)&g_Zex[(size_t)bc*Dd + js*4];
    __syncthreads();

    size_t srow = tokbase * Dd * Dd;
    for (int t=0; t<Lc; t++){
        float4 v = *(const float4*)&g_Vb[(tokbase + t)*Dd + js*4];
        size_t so = srow + (size_t)t*Dd*Dd + js*4;
        #pragma unroll
        for (int a=0;a<4;a++){
            float kk = sk[t*16 + isub*4 + a];
            R[a].x = fmaf(kk, v.x, R[a].x);
            R[a].y = fmaf(kk, v.y, R[a].y);
            R[a].z = fmaf(kk, v.z, R[a].z);
            R[a].w = fmaf(kk, v.w, R[a].w);
            float4 w;
            w.x = clipf(R[a].x); w.y = clipf(R[a].y);
            w.z = clipf(R[a].z); w.w = clipf(R[a].w);
            *(float4*)&Sout[so + (size_t)(ib+a)*Dd] = w;
        }
        if (doZ){
            float4 kv = *(const float4*)&g_Kb[(tokbase + t)*Dd + js*4];
            zr.x += kv.x; zr.y += kv.y; zr.z += kv.z; zr.w += kv.w;
            float4 w;
            w.x = clipf(zr.x); w.y = clipf(zr.y);
            w.z = clipf(zr.z); w.w = clipf(zr.w);
            *(float4*)&Zout[(tokbase + t)*Dd + js*4] = w;
        }
    }
}

// ---------------- K_num : num = Q@Pex + tril(QK^T)@V ; den ; o0 -----------
#define NUM_SMEM_FLOATS (128*129 + 128*33 + 32*128 + 128 + 128)
__global__ __launch_bounds__(256)
void k_num(){
    extern __shared__ float sm[];
    float* aqk = sm;                     // 128*129
    float* As  = aqk + 128*129;          // 128*33
    float* Bs  = As  + 128*33;           // 32*128 (also used transposed)
    float* den = Bs  + 32*128;           // 128
    float* zs  = den + 128;              // 128

    int bc = blockIdx.x;
    int tid = threadIdx.x, tx = tid%16, ty = tid/16;
    size_t tok0 = (size_t)bc * Lc;
    size_t pbase = (size_t)bc*Dd*Dd;

    if (tid < 128) zs[tid] = g_Zex[(size_t)bc*Dd + tid];

    float acc[8][8];
    float qzp[8];
    #pragma unroll
    for (int i=0;i<8;i++){ qzp[i]=0.f;
        #pragma unroll
        for (int j=0;j<8;j++) acc[i][j]=0.f; }
    __syncthreads();

    // ---- stage 1: AQK[t][s] = Q_t . K_s  (k = d) ----
    for (int d0=0; d0<Dd; d0+=32){
        loadA (As, g_Qb + tok0*Dd, d0, Dd);
        loadAT(Bs, g_Kb + tok0*Dd, d0, Dd);
        __syncthreads();
        #pragma unroll
        for (int k=0;k<32;k++){
            float a[8], b[8];
            #pragma unroll
            for (int i=0;i<8;i++) a[i] = As[(ty*8+i)*33 + k];
            *(float4*)&b[0] = *(float4*)&Bs[k*128 + tx*8];
            *(float4*)&b[4] = *(float4*)&Bs[k*128 + tx*8 + 4];
            #pragma unroll
            for (int i=0;i<8;i++)
                #pragma unroll
                for (int j=0;j<8;j++)
                    acc[i][j] = fmaf(a[i], b[j], acc[i][j]);
            if (tx==0){
                float zz = zs[d0+k];
                #pragma unroll
                for (int i=0;i<8;i++) qzp[i] = fmaf(a[i], zz, qzp[i]);
            }
        }
        __syncthreads();
    }
    #pragma unroll
    for (int i=0;i<8;i++){
        int t = ty*8+i;
        #pragma unroll
        for (int j=0;j<8;j++){
            int s = tx*8+j;
            aqk[t*129 + s] = (s<=t) ? acc[i][j] : 0.f;
        }
    }
    if (tx==0){
        #pragma unroll
        for (int i=0;i<8;i++) den[ty*8+i] = qzp[i];
    }
    __syncthreads();
    if (tid < 128){
        float rs = 0.f;
        #pragma unroll 8
        for (int s=0;s<128;s++) rs += aqk[tid*129 + s];
        den[tid] = den[tid] + rs + EPS_DEN;
    }
    __syncthreads();

    // ---- stage 2a: acc = tril(AQK) @ V  (k = s) ----
    #pragma unroll
    for (int i=0;i<8;i++)
        #pragma unroll
        for (int j=0;j<8;j++) acc[i][j]=0.f;

    for (int s0=0; s0<128; s0+=32){
        loadB(Bs, g_Vb + (tok0+s0)*Dd, Dd);
        __syncthreads();
        #pragma unroll
        for (int k=0;k<32;k++){
            int s = s0 + k;
            float a[8], b[8];
            #pragma unroll
            for (int i=0;i<8;i++) a[i] = aqk[(ty*8+i)*129 + s];
            *(float4*)&b[0] = *(float4*)&Bs[k*128 + tx*8];
            *(float4*)&b[4] = *(float4*)&Bs[k*128 + tx*8 + 4];
            #pragma unroll
            for (int i=0;i<8;i++)
                #pragma unroll
                for (int j=0;j<8;j++)
                    acc[i][j] = fmaf(a[i], b[j], acc[i][j]);
        }
        __syncthreads();
    }
    // ---- stage 2b: acc += Q @ Pex  (k = d) ----
    for (int d0=0; d0<Dd; d0+=32){
        loadA(As, g_Qb + tok0*Dd, d0, Dd);
        loadB(Bs, g_Pex + pbase + (size_t)d0*Dd, Dd);
        __syncthreads();
        #pragma unroll
        for (int k=0;k<32;k++){
            float a[8], b[8];
            #pragma unroll
            for (int i=0;i<8;i++) a[i] = As[(ty*8+i)*33 + k];
            *(float4*)&b[0] = *(float4*)&Bs[k*128 + tx*8];
            *(float4*)&b[4] = *(float4*)&Bs[k*128 + tx*8 + 4];
            #pragma unroll
            for (int i=0;i<8;i++)
                #pragma unroll
                for (int j=0;j<8;j++)
                    acc[i][j] = fmaf(a[i], b[j], acc[i][j]);
        }
        __syncthreads();
    }
    // ---- epilogue: o0 = num/den ----
    #pragma unroll
    for (int i=0;i<8;i++){
        float dd = den[ty*8+i];
        float o[8];
        #pragma unroll
        for (int j=0;j<8;j++) o[j] = acc[i][j] / dd;
        size_t ro = (tok0 + ty*8 + i)*Dd + tx*8;
        *(float4*)&g_o0[ro]     = *(float4*)&o[0];
        *(float4*)&g_o0[ro + 4] = *(float4*)&o[4];
    }
}

// ---------------- K_ffn : relu(relu(o0@w1+b1)@w2+b2) + short --------------
#define FFN_SMEM_FLOATS (128*129 + 128*33 + 32*128)
__global__ __launch_bounds__(256)
void k_ffn(const float* __restrict__ w1, const float* __restrict__ b1,
           const float* __restrict__ w2, const float* __restrict__ b2,
           float* __restrict__ outp){
    extern __shared__ float sm[];
    float* hs = sm;                 // 128*129
    float* As = hs + 128*129;       // 128*33
    float* Bs = As + 128*33;        // 32*128

    int tid = threadIdx.x, tx = tid%16, ty = tid/16;
    size_t tok0 = (size_t)blockIdx.x * 128;

    float acc[8][8];
    #pragma unroll
    for (int i=0;i<8;i++)
        #pragma unroll
        for (int j=0;j<8;j++) acc[i][j]=0.f;

    for (int d0=0; d0<Dd; d0+=32){
        loadA(As, g_o0 + tok0*Dd, d0, Dd);
        loadB(Bs, w1 + (size_t)d0*Dd, Dd);
        __syncthreads();
        #pragma unroll
        for (int k=0;k<32;k++){
            float a[8], b[8];
            #pragma unroll
            for (int i=0;i<8;i++) a[i] = As[(ty*8+i)*33 + k];
            *(float4*)&b[0] = *(float4*)&Bs[k*128 + tx*8];
            *(float4*)&b[4] = *(float4*)&Bs[k*128 + tx*8 + 4];
            #pragma unroll
            for (int i=0;i<8;i++)
                #pragma unroll
                for (int j=0;j<8;j++)
                    acc[i][j] = fmaf(a[i], b[j], acc[i][j]);
        }
        __syncthreads();
    }
    #pragma unroll
    for (int i=0;i<8;i++)
        #pragma unroll
        for (int j=0;j<8;j++){
            float h = acc[i][j] + __ldg(&b1[tx*8+j]);
            hs[(ty*8+i)*129 + tx*8+j] = fmaxf(h, 0.f);
        }
    __syncthreads();

    #pragma unroll
    for (int i=0;i<8;i++)
        #pragma unroll
        for (int j=0;j<8;j++) acc[i][j]=0.f;

    for (int d0=0; d0<Dd; d0+=32){
        loadB(Bs, w2 + (size_t)d0*Dd, Dd);
        __syncthreads();
        #pragma unroll
        for (int k=0;k<32;k++){
            float a[8], b[8];
            #pragma unroll
            for (int i=0;i<8;i++) a[i] = hs[(ty*8+i)*129 + d0 + k];
            *(float4*)&b[0] = *(float4*)&Bs[k*128 + tx*8];
            *(float4*)&b[4] = *(float4*)&Bs[k*128 + tx*8 + 4];
            #pragma unroll
            for (int i=0;i<8;i++)
                #pragma unroll
                for (int j=0;j<8;j++)
                    acc[i][j] = fmaf(a[i], b[j], acc[i][j]);
        }
        __syncthreads();
    }
    #pragma unroll
    for (int i=0;i<8;i++){
        size_t t = tok0 + ty*8 + i;
        float o[8];
        #pragma unroll
        for (int j=0;j<8;j++){
            int n = tx*8 + j;
            o[j] = fmaxf(acc[i][j] + __ldg(&b2[n]), 0.f) + g_sh[t*Dd + n];
        }
        *(float4*)&outp[t*Dd + tx*8]     = *(float4*)&o[0];
        *(float4*)&outp[t*Dd + tx*8 + 4] = *(float4*)&o[4];
    }
}

// ---------------- launch ---------------------------------------------------
extern "C" void kernel_launch(void* const* d_in, const int* in_sizes, int n_in,
                              void* d_out, int out_size){
    const float* hist = (const float*)d_in[0];
    const float* S0   = (const float*)d_in[1];
    const float* Z0   = (const float*)d_in[2];
    const float* Wk   = (const float*)d_in[3];
    const float* Wq   = (const float*)d_in[4];
    const float* Wv   = (const float*)d_in[5];
    const float* lng  = (const float*)d_in[6];
    const float* lnb  = (const float*)d_in[7];
    const float* w1   = (const float*)d_in[8];
    const float* b1   = (const float*)d_in[9];
    const float* w2   = (const float*)d_in[10];
    const float* b2   = (const float*)d_in[11];
    const float* scw  = (const float*)d_in[12];
    const float* scb  = (const float*)d_in[13];

    float* out  = (float*)d_out;
    float* Sout = out + (size_t)BT*Dd;
    float* Zout = Sout + (size_t)BT*Dd*Dd;

    long long full = (long long)BT*Dd + (long long)BT*Dd*Dd + (long long)BT*Dd;
    bool writeS = ((long long)out_size >= full);

    cudaFuncSetAttribute(k_num, cudaFuncAttributeMaxDynamicSharedMemorySize,
                         NUM_SMEM_FLOATS*4);
    cudaFuncSetAttribute(k_ffn, cudaFuncAttributeMaxDynamicSharedMemorySize,
                         FFN_SMEM_FLOATS*4);

    k_ln<<<BT, 128>>>(hist, lng, lnb);
    dim3 gp(BT/128, 4);
    k_proj<<<gp, 256>>>(Wk, Wq, Wv, scw, scb);
    k_chunksum<<<NC, 256>>>();
    k_kc<<<NC, 128>>>();
    dim3 gpx(Dd, Bb);
    k_prefix<<<gpx, 128>>>(S0);
    k_zex<<<Bb, 128>>>(Z0);
    if (writeS){
        dim3 gs(8, CC, Bb);
        k_scan<<<gs, 128>>>(Sout, Zout);
    }
    k_num<<<NC, 256, NUM_SMEM_FLOATS*4>>>();
    k_ffn<<<BT/128, 256, FFN_SMEM_FLOATS*4>>>(w1, b1, w2, b2, out);
}

// round 3
// speedup vs baseline: 1.1302x; 1.1302x over previous
#include <cuda_runtime.h>
#include <cuda_bf16.h>
#include <stdint.h>
#include <math.h>

#define Bb 4
#define Tt 2048
#define Ff 512
#define Dd 128
#define BT (Bb*Tt)          // 8192
#define Lc 128              // chunk length
#define CC 16               // chunks per batch
#define NC (Bb*CC)          // 64 total chunks

#define CLAMP_V 1e20f
#define EPS_LN 1e-5f
#define EPS_DEN 1e-5f

// ---------------- scratch (device globals; no allocation allowed) ----------
__device__ __nv_bfloat16 g_xh[BT*Ff];   // hi(xn)   8 MB
__device__ __nv_bfloat16 g_xl[BT*Ff];   // lo(xn)   8 MB
__device__ __nv_bfloat16 g_WhT[4][Dd*Ff]; // W^T hi bf16 (n-major, k contig)
__device__ __nv_bfloat16 g_WlT[4][Dd*Ff]; // W^T lo
__device__ float g_Kb[BT*Dd];        // K = phi(x Wk)          4 MB
__device__ float g_Qb[BT*Dd];        // Q = phi(x Wq)          4 MB
__device__ float g_Vb[BT*Dd];        // V = x Wv               4 MB
__device__ float g_sh[BT*Dd];        // shortcut x sc_w + b    4 MB
__device__ float g_KVc[NC*Dd*Dd];    // per-chunk KV sums      4 MB
__device__ float g_Pex[NC*Dd*Dd];    // exclusive prefixes (+S0) 4 MB
__device__ float g_Kc[NC*Dd];        // per-chunk K sums
__device__ float g_Zex[NC*Dd];       // exclusive Z prefixes (+Z0)
__device__ float g_o0[BT*Dd];        // num/den                4 MB

__device__ __forceinline__ float clipf(float x){
    return fminf(fmaxf(x, -CLAMP_V), CLAMP_V);
}

__device__ __forceinline__ void mma16816(float* c,
    const uint32_t* a, const uint32_t* b){
    asm volatile("mma.sync.aligned.m16n8k16.row.col.f32.bf16.bf16.f32 "
        "{%0,%1,%2,%3}, {%4,%5,%6,%7}, {%8,%9}, {%0,%1,%2,%3};\n"
        : "+f"(c[0]),"+f"(c[1]),"+f"(c[2]),"+f"(c[3])
        : "r"(a[0]),"r"(a[1]),"r"(a[2]),"r"(a[3]), "r"(b[0]),"r"(b[1]));
}

// ---------------- K_ln : LayerNorm -> split bf16 hi/lo --------------------
__global__ void k_ln(const float* __restrict__ hist,
                     const float* __restrict__ lng,
                     const float* __restrict__ lnb){
    int row = blockIdx.x;             // 0..BT-1
    int tid = threadIdx.x;            // 128 threads, 4 floats each
    const float4* hp = (const float4*)(hist + (size_t)row*Ff);
    float4 v = hp[tid];
    float s  = v.x+v.y+v.z+v.w;
    float sq = v.x*v.x+v.y*v.y+v.z*v.z+v.w*v.w;
    #pragma unroll
    for (int o=16;o;o>>=1){
        s  += __shfl_down_sync(0xffffffffu, s,  o);
        sq += __shfl_down_sync(0xffffffffu, sq, o);
    }
    __shared__ float ss[4], sqs[4];
    if ((tid&31)==0){ ss[tid>>5]=s; sqs[tid>>5]=sq; }
    __syncthreads();
    s  = ss[0]+ss[1]+ss[2]+ss[3];
    sq = sqs[0]+sqs[1]+sqs[2]+sqs[3];
    float mu  = s*(1.0f/Ff);
    float var = sq*(1.0f/Ff) - mu*mu;
    float inv = rsqrtf(var + EPS_LN);
    float4 g4 = ((const float4*)lng)[tid];
    float4 b4 = ((const float4*)lnb)[tid];
    float o[4];
    o[0] = (v.x-mu)*inv*g4.x + b4.x;
    o[1] = (v.y-mu)*inv*g4.y + b4.y;
    o[2] = (v.z-mu)*inv*g4.z + b4.z;
    o[3] = (v.w-mu)*inv*g4.w + b4.w;
    __nv_bfloat16 h[4], l[4];
    #pragma unroll
    for (int i=0;i<4;i++){
        h[i] = __float2bfloat16_rn(o[i]);
        l[i] = __float2bfloat16_rn(o[i] - __bfloat162float(h[i]));
    }
    *(uint2*)(g_xh + (size_t)row*Ff + tid*4) = *(uint2*)h;
    *(uint2*)(g_xl + (size_t)row*Ff + tid*4) = *(uint2*)l;
}

// ---------------- K_wconv : W[512][128] -> W^T hi/lo bf16 [128][512] ------
__global__ void k_wconv(const float* __restrict__ Wk, const float* __restrict__ Wq,
                        const float* __restrict__ Wv, const float* __restrict__ scw){
    __shared__ float tile[32][33];
    int mid = blockIdx.z;
    const float* W = (mid==0)?Wk:(mid==1)?Wq:(mid==2)?Wv:scw;
    int k0 = blockIdx.x*32, n0 = blockIdx.y*32;
    int tx = threadIdx.x, ty = threadIdx.y;   // 32 x 8
    #pragma unroll
    for (int r=0;r<32;r+=8)
        tile[ty+r][tx] = W[(size_t)(k0+ty+r)*Dd + n0 + tx];
    __syncthreads();
    #pragma unroll
    for (int r=0;r<32;r+=8){
        int n = n0 + ty + r, k = k0 + tx;
        float v = tile[tx][ty+r];
        __nv_bfloat16 h = __float2bfloat16_rn(v);
        __nv_bfloat16 l = __float2bfloat16_rn(v - __bfloat162float(h));
        g_WhT[mid][(size_t)n*Ff + k] = h;
        g_WlT[mid][(size_t)n*Ff + k] = l;
    }
}

// ---------------- K_proj : tensor-core split-bf16 GEMM + activations ------
// block: 128 rows x 128 cols, 256 threads = 8 warps (2x4), warp tile 64x32
#define KT 32
#define SSTR 40   // bf16 stride (80B, 16B aligned)
__global__ __launch_bounds__(256)
void k_proj(const float* __restrict__ scb){
    __shared__ __nv_bfloat16 Ah[128*SSTR];
    __shared__ __nv_bfloat16 Al[128*SSTR];
    __shared__ __nv_bfloat16 Bh[128*SSTR];
    __shared__ __nv_bfloat16 Bl[128*SSTR];

    int mid = blockIdx.y;    // 0:K 1:Q 2:V 3:short
    int m0  = blockIdx.x * 128;
    float* outp = (mid==0)?g_Kb:(mid==1)?g_Qb:(mid==2)?g_Vb:g_sh;
    const __nv_bfloat16* WhT = g_WhT[mid];
    const __nv_bfloat16* WlT = g_WlT[mid];

    int tid = threadIdx.x;
    int warp = tid>>5, lane = tid&31;
    int wm = warp>>2, wn = warp&3;       // warp tile: rows wm*64, cols wn*32
    int g = lane>>2, tig = lane&3;

    float acc[4][4][4];
    #pragma unroll
    for (int i=0;i<4;i++)
        #pragma unroll
        for (int j=0;j<4;j++)
            #pragma unroll
            for (int r=0;r<4;r++) acc[i][j][r]=0.f;

    int lr = tid>>1;            // load row 0..127
    int lc = (tid&1)*2;         // uint4 chunk 0/2 (each uint4 = 8 bf16)

    for (int k0=0; k0<Ff; k0+=KT){
        const uint4* asrc_h = (const uint4*)(g_xh + (size_t)(m0+lr)*Ff + k0);
        const uint4* asrc_l = (const uint4*)(g_xl + (size_t)(m0+lr)*Ff + k0);
        const uint4* bsrc_h = (const uint4*)(WhT  + (size_t)lr*Ff + k0);
        const uint4* bsrc_l = (const uint4*)(WlT  + (size_t)lr*Ff + k0);
        uint4* adst_h = (uint4*)(Ah + lr*SSTR);
        uint4* adst_l = (uint4*)(Al + lr*SSTR);
        uint4* bdst_h = (uint4*)(Bh + lr*SSTR);
        uint4* bdst_l = (uint4*)(Bl + lr*SSTR);
        #pragma unroll
        for (int c=0;c<2;c++){
            adst_h[lc+c] = asrc_h[lc+c];
            adst_l[lc+c] = asrc_l[lc+c];
            bdst_h[lc+c] = bsrc_h[lc+c];
            bdst_l[lc+c] = bsrc_l[lc+c];
        }
        __syncthreads();

        const uint32_t* AhU = (const uint32_t*)Ah;
        const uint32_t* AlU = (const uint32_t*)Al;
        const uint32_t* BhU = (const uint32_t*)Bh;
        const uint32_t* BlU = (const uint32_t*)Bl;
        #pragma unroll
        for (int kk=0; kk<KT/2; kk+=8){   // kk in u32 units: 0, 8
            uint32_t ahf[4][4], alf[4][4], bhf[4][2], blf[4][2];
            #pragma unroll
            for (int i=0;i<4;i++){
                int rb = (wm*64 + i*16 + g)*(SSTR/2) + kk + tig;
                ahf[i][0] = AhU[rb];
                ahf[i][1] = AhU[rb + 8*(SSTR/2)];
                ahf[i][2] = AhU[rb + 4];
                ahf[i][3] = AhU[rb + 8*(SSTR/2) + 4];
                alf[i][0] = AlU[rb];
                alf[i][1] = AlU[rb + 8*(SSTR/2)];
                alf[i][2] = AlU[rb + 4];
                alf[i][3] = AlU[rb + 8*(SSTR/2) + 4];
            }
            #pragma unroll
            for (int j=0;j<4;j++){
                int rb = (wn*32 + j*8 + g)*(SSTR/2) + kk + tig;
                bhf[j][0] = BhU[rb];
                bhf[j][1] = BhU[rb + 4];
                blf[j][0] = BlU[rb];
                blf[j][1] = BlU[rb + 4];
            }
            #pragma unroll
            for (int i=0;i<4;i++)
                #pragma unroll
                for (int j=0;j<4;j++)
                    mma16816(acc[i][j], ahf[i], bhf[j]);
            #pragma unroll
            for (int i=0;i<4;i++)
                #pragma unroll
                for (int j=0;j<4;j++)
                    mma16816(acc[i][j], ahf[i], blf[j]);
            #pragma unroll
            for (int i=0;i<4;i++)
                #pragma unroll
                for (int j=0;j<4;j++)
                    mma16816(acc[i][j], alf[i], bhf[j]);
        }
        __syncthreads();
    }

    // epilogue
    #pragma unroll
    for (int i=0;i<4;i++){
        #pragma unroll
        for (int j=0;j<4;j++){
            int m = m0 + wm*64 + i*16 + g;
            int n = wn*32 + j*8 + 2*tig;
            float v[4];
            #pragma unroll
            for (int r=0;r<4;r++) v[r] = acc[i][j][r];
            if (mid<=1){
                #pragma unroll
                for (int r=0;r<4;r++) v[r] = (v[r]>0.f) ? v[r]+1.f : expf(v[r]);
            } else if (mid==3){
                v[0] += __ldg(&scb[n]);   v[1] += __ldg(&scb[n+1]);
                v[2] += __ldg(&scb[n]);   v[3] += __ldg(&scb[n+1]);
            }
            *(float2*)&outp[(size_t)m*Dd + n]     = make_float2(v[0], v[1]);
            *(float2*)&outp[(size_t)(m+8)*Dd + n] = make_float2(v[2], v[3]);
        }
    }
}

// ---------------- shared tile loaders (256-thread blocks) -----------------
__device__ __forceinline__ void loadA(float* As, const float* __restrict__ src,
                                      int d0, int stride){
    int tid = threadIdx.x;
    int r = tid/8, c4 = (tid%8)*4;
    #pragma unroll
    for (int rr=0; rr<128; rr+=32){
        float4 v = *(const float4*)&src[(size_t)(rr+r)*stride + d0 + c4];
        As[(rr+r)*33 + c4+0] = v.x;
        As[(rr+r)*33 + c4+1] = v.y;
        As[(rr+r)*33 + c4+2] = v.z;
        As[(rr+r)*33 + c4+3] = v.w;
    }
}
__device__ __forceinline__ void loadAT(float* dst, const float* __restrict__ src,
                                       int d0, int stride){
    int tid = threadIdx.x;
    int r = tid/8, c4 = (tid%8)*4;
    #pragma unroll
    for (int rr=0; rr<128; rr+=32){
        float4 v = *(const float4*)&src[(size_t)(rr+r)*stride + d0 + c4];
        dst[(c4+0)*128 + rr+r] = v.x;
        dst[(c4+1)*128 + rr+r] = v.y;
        dst[(c4+2)*128 + rr+r] = v.z;
        dst[(c4+3)*128 + rr+r] = v.w;
    }
}
__device__ __forceinline__ void loadB(float* Bs, const float* __restrict__ src,
                                      int stride){
    int tid = threadIdx.x;
    int r = tid/32, c4 = (tid%32)*4;
    #pragma unroll
    for (int rr=0; rr<32; rr+=8)
        *(float4*)&Bs[(rr+r)*128 + c4] =
            *(const float4*)&src[(size_t)(rr+r)*stride + c4];
}

// ---------------- K_chunksum : per-chunk sum of K_t (x) V_t ---------------
__global__ __launch_bounds__(256)
void k_chunksum(){
    __shared__ float Ks[32*128];
    __shared__ float Vs[32*128];
    int bc = blockIdx.x;
    int tid = threadIdx.x, tx = tid%16, ty = tid/16;
    size_t base = (size_t)bc * Lc * Dd;
    float acc[8][8];
    #pragma unroll
    for (int i=0;i<8;i++)
        #pragma unroll
        for (int j=0;j<8;j++) acc[i][j]=0.f;

    for (int tt=0; tt<Lc; tt+=32){
        loadB(Ks, g_Kb + base + (size_t)tt*Dd, Dd);
        loadB(Vs, g_Vb + base + (size_t)tt*Dd, Dd);
        __syncthreads();
        #pragma unroll
        for (int s=0;s<32;s++){
            float a[8], b[8];
            #pragma unroll
            for (int i=0;i<8;i++) a[i] = Ks[s*128 + ty*8 + i];
            *(float4*)&b[0] = *(float4*)&Vs[s*128 + tx*8];
            *(float4*)&b[4] = *(float4*)&Vs[s*128 + tx*8 + 4];
            #pragma unroll
            for (int i=0;i<8;i++)
                #pragma unroll
                for (int j=0;j<8;j++)
                    acc[i][j] = fmaf(a[i], b[j], acc[i][j]);
        }
        __syncthreads();
    }
    size_t ob = (size_t)bc*Dd*Dd;
    #pragma unroll
    for (int i=0;i<8;i++){
        *(float4*)&g_KVc[ob + (size_t)(ty*8+i)*Dd + tx*8]     = *(float4*)&acc[i][0];
        *(float4*)&g_KVc[ob + (size_t)(ty*8+i)*Dd + tx*8 + 4] = *(float4*)&acc[i][4];
    }
}

// ---------------- K_kc : per-chunk sums of K (512 threads) ----------------
__global__ void k_kc(){
    __shared__ float part[4][128];
    int bc = blockIdx.x; int tid = threadIdx.x;
    int ts = tid>>7, d = tid&127;
    size_t base = ((size_t)bc*Lc + ts*32)*Dd + d;
    float a=0.f;
    #pragma unroll
    for (int t=0;t<32;t++) a += g_Kb[base + (size_t)t*Dd];
    part[ts][d] = a;
    __syncthreads();
    if (tid < 128)
        g_Kc[bc*Dd + tid] = (part[0][tid]+part[1][tid])+(part[2][tid]+part[3][tid]);
}

// ---------------- K_prefix : exclusive prefix of KV chunk sums (+S0) ------
__global__ void k_prefix(const float* __restrict__ S0){
    int i = blockIdx.x, b = blockIdx.y, j = threadIdx.x;
    float r = S0[((size_t)b*Dd + i)*Dd + j];
    for (int c=0;c<CC;c++){
        size_t idx = ((size_t)(b*CC+c)*Dd + i)*Dd + j;
        g_Pex[idx] = r;
        r += g_KVc[idx];
    }
}

// ---------------- K_zex : exclusive prefix of K chunk sums (+Z0) ----------
__global__ void k_zex(const float* __restrict__ Z0){
    int b = blockIdx.x, d = threadIdx.x;
    float r = Z0[b*Dd + d];
    for (int c=0;c<CC;c++){
        g_Zex[(b*CC+c)*Dd + d] = r;
        r += g_Kc[(b*CC+c)*Dd + d];
    }
}

// ---------------- K_scan : intra-chunk scan, streams S (and Z) out --------
__global__ __launch_bounds__(128)
void k_scan(float* __restrict__ Sout, float* __restrict__ Zout){
    int g = blockIdx.x;   // 8 groups of 16 i-rows
    int c = blockIdx.y;   // chunk
    int b = blockIdx.z;   // batch
    int tid = threadIdx.x;
    int js = tid & 31;
    int isub = tid >> 5;
    int ib = g*16 + isub*4;
    int bc = b*CC + c;
    size_t tokbase = (size_t)bc * Lc;

    __shared__ float sk[128*16];
    for (int idx = tid; idx < 128*16; idx += 128){
        int t_ = idx >> 4, i_ = idx & 15;
        sk[idx] = g_Kb[(tokbase + t_)*Dd + g*16 + i_];
    }

    float4 R[4];
    size_t pbase = (size_t)bc*Dd*Dd;
    #pragma unroll
    for (int a=0;a<4;a++)
        R[a] = *(const float4*)&g_Pex[pbase + (size_t)(ib+a)*Dd + js*4];

    bool doZ = (g==0 && isub==0);
    float4 zr = make_float4(0,0,0,0);
    if (doZ) zr = *(const float4*)&g_Zex[(size_t)bc*Dd + js*4];
    __syncthreads();

    size_t srow = tokbase * Dd * Dd;
    for (int t=0; t<Lc; t++){
        float4 v = *(const float4*)&g_Vb[(tokbase + t)*Dd + js*4];
        size_t so = srow + (size_t)t*Dd*Dd + js*4;
        #pragma unroll
        for (int a=0;a<4;a++){
            float kk = sk[t*16 + isub*4 + a];
            R[a].x = fmaf(kk, v.x, R[a].x);
            R[a].y = fmaf(kk, v.y, R[a].y);
            R[a].z = fmaf(kk, v.z, R[a].z);
            R[a].w = fmaf(kk, v.w, R[a].w);
            float4 w;
            w.x = clipf(R[a].x); w.y = clipf(R[a].y);
            w.z = clipf(R[a].z); w.w = clipf(R[a].w);
            *(float4*)&Sout[so + (size_t)(ib+a)*Dd] = w;
        }
        if (doZ){
            float4 kv = *(const float4*)&g_Kb[(tokbase + t)*Dd + js*4];
            zr.x += kv.x; zr.y += kv.y; zr.z += kv.z; zr.w += kv.w;
            float4 w;
            w.x = clipf(zr.x); w.y = clipf(zr.y);
            w.z = clipf(zr.z); w.w = clipf(zr.w);
            *(float4*)&Zout[(tokbase + t)*Dd + js*4] = w;
        }
    }
}

// ---------------- K_num : num = Q@Pex + tril(QK^T)@V ; den ; o0 -----------
#define NUM_SMEM_FLOATS (128*129 + 128*33 + 32*128 + 128 + 128)
__global__ __launch_bounds__(256)
void k_num(){
    extern __shared__ float sm[];
    float* aqk = sm;                     // 128*129
    float* As  = aqk + 128*129;          // 128*33
    float* Bs  = As  + 128*33;           // 32*128
    float* den = Bs  + 32*128;           // 128
    float* zs  = den + 128;              // 128

    int bc = blockIdx.x;
    int tid = threadIdx.x, tx = tid%16, ty = tid/16;
    size_t tok0 = (size_t)bc * Lc;
    size_t pbase = (size_t)bc*Dd*Dd;

    if (tid < 128) zs[tid] = g_Zex[(size_t)bc*Dd + tid];

    float acc[8][8];
    float qzp[8];
    #pragma unroll
    for (int i=0;i<8;i++){ qzp[i]=0.f;
        #pragma unroll
        for (int j=0;j<8;j++) acc[i][j]=0.f; }
    __syncthreads();

    for (int d0=0; d0<Dd; d0+=32){
        loadA (As, g_Qb + tok0*Dd, d0, Dd);
        loadAT(Bs, g_Kb + tok0*Dd, d0, Dd);
        __syncthreads();
        #pragma unroll
        for (int k=0;k<32;k++){
            float a[8], b[8];
            #pragma unroll
            for (int i=0;i<8;i++) a[i] = As[(ty*8+i)*33 + k];
            *(float4*)&b[0] = *(float4*)&Bs[k*128 + tx*8];
            *(float4*)&b[4] = *(float4*)&Bs[k*128 + tx*8 + 4];
            #pragma unroll
            for (int i=0;i<8;i++)
                #pragma unroll
                for (int j=0;j<8;j++)
                    acc[i][j] = fmaf(a[i], b[j], acc[i][j]);
            if (tx==0){
                float zz = zs[d0+k];
                #pragma unroll
                for (int i=0;i<8;i++) qzp[i] = fmaf(a[i], zz, qzp[i]);
            }
        }
        __syncthreads();
    }
    #pragma unroll
    for (int i=0;i<8;i++){
        int t = ty*8+i;
        #pragma unroll
        for (int j=0;j<8;j++){
            int s = tx*8+j;
            aqk[t*129 + s] = (s<=t) ? acc[i][j] : 0.f;
        }
    }
    if (tx==0){
        #pragma unroll
        for (int i=0;i<8;i++) den[ty*8+i] = qzp[i];
    }
    __syncthreads();
    if (tid < 128){
        float rs = 0.f;
        #pragma unroll 8
        for (int s=0;s<128;s++) rs += aqk[tid*129 + s];
        den[tid] = den[tid] + rs + EPS_DEN;
    }
    __syncthreads();

    #pragma unroll
    for (int i=0;i<8;i++)
        #pragma unroll
        for (int j=0;j<8;j++) acc[i][j]=0.f;

    for (int s0=0; s0<128; s0+=32){
        loadB(Bs, g_Vb + (tok0+s0)*Dd, Dd);
        __syncthreads();
        #pragma unroll
        for (int k=0;k<32;k++){
            int s = s0 + k;
            float a[8], b[8];
            #pragma unroll
            for (int i=0;i<8;i++) a[i] = aqk[(ty*8+i)*129 + s];
            *(float4*)&b[0] = *(float4*)&Bs[k*128 + tx*8];
            *(float4*)&b[4] = *(float4*)&Bs[k*128 + tx*8 + 4];
            #pragma unroll
            for (int i=0;i<8;i++)
                #pragma unroll
                for (int j=0;j<8;j++)
                    acc[i][j] = fmaf(a[i], b[j], acc[i][j]);
        }
        __syncthreads();
    }
    for (int d0=0; d0<Dd; d0+=32){
        loadA(As, g_Qb + tok0*Dd, d0, Dd);
        loadB(Bs, g_Pex + pbase + (size_t)d0*Dd, Dd);
        __syncthreads();
        #pragma unroll
        for (int k=0;k<32;k++){
            float a[8], b[8];
            #pragma unroll
            for (int i=0;i<8;i++) a[i] = As[(ty*8+i)*33 + k];
            *(float4*)&b[0] = *(float4*)&Bs[k*128 + tx*8];
            *(float4*)&b[4] = *(float4*)&Bs[k*128 + tx*8 + 4];
            #pragma unroll
            for (int i=0;i<8;i++)
                #pragma unroll
                for (int j=0;j<8;j++)
                    acc[i][j] = fmaf(a[i], b[j], acc[i][j]);
        }
        __syncthreads();
    }
    #pragma unroll
    for (int i=0;i<8;i++){
        float dd = den[ty*8+i];
        float o[8];
        #pragma unroll
        for (int j=0;j<8;j++) o[j] = acc[i][j] / dd;
        size_t ro = (tok0 + ty*8 + i)*Dd + tx*8;
        *(float4*)&g_o0[ro]     = *(float4*)&o[0];
        *(float4*)&g_o0[ro + 4] = *(float4*)&o[4];
    }
}

// ---------------- K_ffn : relu(relu(o0@w1+b1)@w2+b2) + short --------------
#define FFN_SMEM_FLOATS (128*129 + 128*33 + 32*128)
__global__ __launch_bounds__(256)
void k_ffn(const float* __restrict__ w1, const float* __restrict__ b1,
           const float* __restrict__ w2, const float* __restrict__ b2,
           float* __restrict__ outp){
    extern __shared__ float sm[];
    float* hs = sm;
    float* As = hs + 128*129;
    float* Bs = As + 128*33;

    int tid = threadIdx.x, tx = tid%16, ty = tid/16;
    size_t tok0 = (size_t)blockIdx.x * 128;

    float acc[8][8];
    #pragma unroll
    for (int i=0;i<8;i++)
        #pragma unroll
        for (int j=0;j<8;j++) acc[i][j]=0.f;

    for (int d0=0; d0<Dd; d0+=32){
        loadA(As, g_o0 + tok0*Dd, d0, Dd);
        loadB(Bs, w1 + (size_t)d0*Dd, Dd);
        __syncthreads();
        #pragma unroll
        for (int k=0;k<32;k++){
            float a[8], b[8];
            #pragma unroll
            for (int i=0;i<8;i++) a[i] = As[(ty*8+i)*33 + k];
            *(float4*)&b[0] = *(float4*)&Bs[k*128 + tx*8];
            *(float4*)&b[4] = *(float4*)&Bs[k*128 + tx*8 + 4];
            #pragma unroll
            for (int i=0;i<8;i++)
                #pragma unroll
                for (int j=0;j<8;j++)
                    acc[i][j] = fmaf(a[i], b[j], acc[i][j]);
        }
        __syncthreads();
    }
    #pragma unroll
    for (int i=0;i<8;i++)
        #pragma unroll
        for (int j=0;j<8;j++){
            float h = acc[i][j] + __ldg(&b1[tx*8+j]);
            hs[(ty*8+i)*129 + tx*8+j] = fmaxf(h, 0.f);
        }
    __syncthreads();

    #pragma unroll
    for (int i=0;i<8;i++)
        #pragma unroll
        for (int j=0;j<8;j++) acc[i][j]=0.f;

    for (int d0=0; d0<Dd; d0+=32){
        loadB(Bs, w2 + (size_t)d0*Dd, Dd);
        __syncthreads();
        #pragma unroll
        for (int k=0;k<32;k++){
            float a[8], b[8];
            #pragma unroll
            for (int i=0;i<8;i++) a[i] = hs[(ty*8+i)*129 + d0 + k];
            *(float4*)&b[0] = *(float4*)&Bs[k*128 + tx*8];
            *(float4*)&b[4] = *(float4*)&Bs[k*128 + tx*8 + 4];
            #pragma unroll
            for (int i=0;i<8;i++)
                #pragma unroll
                for (int j=0;j<8;j++)
                    acc[i][j] = fmaf(a[i], b[j], acc[i][j]);
        }
        __syncthreads();
    }
    #pragma unroll
    for (int i=0;i<8;i++){
        size_t t = tok0 + ty*8 + i;
        float o[8];
        #pragma unroll
        for (int j=0;j<8;j++){
            int n = tx*8 + j;
            o[j] = fmaxf(acc[i][j] + __ldg(&b2[n]), 0.f) + g_sh[t*Dd + n];
        }
        *(float4*)&outp[t*Dd + tx*8]     = *(float4*)&o[0];
        *(float4*)&outp[t*Dd + tx*8 + 4] = *(float4*)&o[4];
    }
}

// ---------------- launch ---------------------------------------------------
extern "C" void kernel_launch(void* const* d_in, const int* in_sizes, int n_in,
                              void* d_out, int out_size){
    const float* hist = (const float*)d_in[0];
    const float* S0   = (const float*)d_in[1];
    const float* Z0   = (const float*)d_in[2];
    const float* Wk   = (const float*)d_in[3];
    const float* Wq   = (const float*)d_in[4];
    const float* Wv   = (const float*)d_in[5];
    const float* lng  = (const float*)d_in[6];
    const float* lnb  = (const float*)d_in[7];
    const float* w1   = (const float*)d_in[8];
    const float* b1   = (const float*)d_in[9];
    const float* w2   = (const float*)d_in[10];
    const float* b2   = (const float*)d_in[11];
    const float* scw  = (const float*)d_in[12];
    const float* scb  = (const float*)d_in[13];

    float* out  = (float*)d_out;
    float* Sout = out + (size_t)BT*Dd;
    float* Zout = Sout + (size_t)BT*Dd*Dd;

    long long full = (long long)BT*Dd + (long long)BT*Dd*Dd + (long long)BT*Dd;
    bool writeS = ((long long)out_size >= full);

    cudaFuncSetAttribute(k_num, cudaFuncAttributeMaxDynamicSharedMemorySize,
                         NUM_SMEM_FLOATS*4);
    cudaFuncSetAttribute(k_ffn, cudaFuncAttributeMaxDynamicSharedMemorySize,
                         FFN_SMEM_FLOATS*4);

    k_ln<<<BT, 128>>>(hist, lng, lnb);
    dim3 gw(Ff/32, Dd/32, 4);
    k_wconv<<<gw, dim3(32,8)>>>(Wk, Wq, Wv, scw);
    dim3 gp(BT/128, 4);
    k_proj<<<gp, 256>>>(scb);
    k_chunksum<<<NC, 256>>>();
    k_kc<<<NC, 512>>>();
    dim3 gpx(Dd, Bb);
    k_prefix<<<gpx, 128>>>(S0);
    k_zex<<<Bb, 128>>>(Z0);
    if (writeS){
        dim3 gs(8, CC, Bb);
        k_scan<<<gs, 128>>>(Sout, Zout);
    }
    k_num<<<NC, 256, NUM_SMEM_FLOATS*4>>>();
    k_ffn<<<BT/128, 256, FFN_SMEM_FLOATS*4>>>(w1, b1, w2, b2, out);
}

// round 4
// speedup vs baseline: 1.4085x; 1.2462x over previous
#include <cuda_runtime.h>
#include <cuda_bf16.h>
#include <stdint.h>
#include <math.h>

#define Bb 4
#define Tt 2048
#define Ff 512
#define Dd 128
#define BT (Bb*Tt)          // 8192
#define Lc 128              // chunk length
#define CC 16               // chunks per batch
#define NC (Bb*CC)          // 64 total chunks
#define NSCAN (NC*4)        // scan blocks in fused tail (4 per chunk)

#define CLAMP_V 1e20f
#define EPS_LN 1e-5f
#define EPS_DEN 1e-5f

// ---------------- scratch (device globals; no allocation allowed) ----------
__device__ __nv_bfloat16 g_xh[BT*Ff];   // hi(xn)   8 MB
__device__ __nv_bfloat16 g_xl[BT*Ff];   // lo(xn)   8 MB
__device__ __nv_bfloat16 g_WhT[4][Dd*Ff]; // W^T hi bf16 (n-major, k contig)
__device__ __nv_bfloat16 g_WlT[4][Dd*Ff]; // W^T lo
__device__ float g_Kb[BT*Dd];        // K = phi(x Wk)          4 MB
__device__ float g_Qb[BT*Dd];        // Q = phi(x Wq)          4 MB
__device__ float g_Vb[BT*Dd];        // V = x Wv               4 MB
__device__ float g_sh[BT*Dd];        // shortcut x sc_w + b    4 MB
__device__ float g_KVp[NC*4*Dd*Dd];  // per-subchunk KV partial sums 16 MB
__device__ float g_Pex[NC*Dd*Dd];    // exclusive prefixes (+S0) 4 MB
__device__ float g_Kc[NC*Dd];        // per-chunk K sums
__device__ float g_Zex[NC*Dd];       // exclusive Z prefixes (+Z0)

__device__ __forceinline__ float clipf(float x){
    return fminf(fmaxf(x, -CLAMP_V), CLAMP_V);
}

__device__ __forceinline__ void mma16816(float* c,
    const uint32_t* a, const uint32_t* b){
    asm volatile("mma.sync.aligned.m16n8k16.row.col.f32.bf16.bf16.f32 "
        "{%0,%1,%2,%3}, {%4,%5,%6,%7}, {%8,%9}, {%0,%1,%2,%3};\n"
        : "+f"(c[0]),"+f"(c[1]),"+f"(c[2]),"+f"(c[3])
        : "r"(a[0]),"r"(a[1]),"r"(a[2]),"r"(a[3]), "r"(b[0]),"r"(b[1]));
}

// ---------------- K_ln : LayerNorm -> split bf16 hi/lo --------------------
__global__ void k_ln(const float* __restrict__ hist,
                     const float* __restrict__ lng,
                     const float* __restrict__ lnb){
    int row = blockIdx.x;
    int tid = threadIdx.x;            // 128 threads, 4 floats each
    const float4* hp = (const float4*)(hist + (size_t)row*Ff);
    float4 v = hp[tid];
    float s  = v.x+v.y+v.z+v.w;
    float sq = v.x*v.x+v.y*v.y+v.z*v.z+v.w*v.w;
    #pragma unroll
    for (int o=16;o;o>>=1){
        s  += __shfl_down_sync(0xffffffffu, s,  o);
        sq += __shfl_down_sync(0xffffffffu, sq, o);
    }
    __shared__ float ss[4], sqs[4];
    if ((tid&31)==0){ ss[tid>>5]=s; sqs[tid>>5]=sq; }
    __syncthreads();
    s  = ss[0]+ss[1]+ss[2]+ss[3];
    sq = sqs[0]+sqs[1]+sqs[2]+sqs[3];
    float mu  = s*(1.0f/Ff);
    float var = sq*(1.0f/Ff) - mu*mu;
    float inv = rsqrtf(var + EPS_LN);
    float4 g4 = ((const float4*)lng)[tid];
    float4 b4 = ((const float4*)lnb)[tid];
    float o[4];
    o[0] = (v.x-mu)*inv*g4.x + b4.x;
    o[1] = (v.y-mu)*inv*g4.y + b4.y;
    o[2] = (v.z-mu)*inv*g4.z + b4.z;
    o[3] = (v.w-mu)*inv*g4.w + b4.w;
    __nv_bfloat16 h[4], l[4];
    #pragma unroll
    for (int i=0;i<4;i++){
        h[i] = __float2bfloat16_rn(o[i]);
        l[i] = __float2bfloat16_rn(o[i] - __bfloat162float(h[i]));
    }
    *(uint2*)(g_xh + (size_t)row*Ff + tid*4) = *(uint2*)h;
    *(uint2*)(g_xl + (size_t)row*Ff + tid*4) = *(uint2*)l;
}

// ---------------- K_wconv : W[512][128] -> W^T hi/lo bf16 [128][512] ------
__global__ void k_wconv(const float* __restrict__ Wk, const float* __restrict__ Wq,
                        const float* __restrict__ Wv, const float* __restrict__ scw){
    __shared__ float tile[32][33];
    int mid = blockIdx.z;
    const float* W = (mid==0)?Wk:(mid==1)?Wq:(mid==2)?Wv:scw;
    int k0 = blockIdx.x*32, n0 = blockIdx.y*32;
    int tx = threadIdx.x, ty = threadIdx.y;   // 32 x 8
    #pragma unroll
    for (int r=0;r<32;r+=8)
        tile[ty+r][tx] = W[(size_t)(k0+ty+r)*Dd + n0 + tx];
    __syncthreads();
    #pragma unroll
    for (int r=0;r<32;r+=8){
        int n = n0 + ty + r, k = k0 + tx;
        float v = tile[tx][ty+r];
        __nv_bfloat16 h = __float2bfloat16_rn(v);
        __nv_bfloat16 l = __float2bfloat16_rn(v - __bfloat162float(h));
        g_WhT[mid][(size_t)n*Ff + k] = h;
        g_WlT[mid][(size_t)n*Ff + k] = l;
    }
}

// ---------------- K_proj : tensor-core split-bf16 GEMM + activations ------
#define KT 32
#define SSTR 40   // bf16 stride (80B, 16B aligned)
__global__ __launch_bounds__(256)
void k_proj(const float* __restrict__ scb){
    __shared__ __nv_bfloat16 Ah[128*SSTR];
    __shared__ __nv_bfloat16 Al[128*SSTR];
    __shared__ __nv_bfloat16 Bh[128*SSTR];
    __shared__ __nv_bfloat16 Bl[128*SSTR];

    int mid = blockIdx.y;    // 0:K 1:Q 2:V 3:short
    int m0  = blockIdx.x * 128;
    float* outp = (mid==0)?g_Kb:(mid==1)?g_Qb:(mid==2)?g_Vb:g_sh;
    const __nv_bfloat16* WhT = g_WhT[mid];
    const __nv_bfloat16* WlT = g_WlT[mid];

    int tid = threadIdx.x;
    int warp = tid>>5, lane = tid&31;
    int wm = warp>>2, wn = warp&3;
    int g = lane>>2, tig = lane&3;

    float acc[4][4][4];
    #pragma unroll
    for (int i=0;i<4;i++)
        #pragma unroll
        for (int j=0;j<4;j++)
            #pragma unroll
            for (int r=0;r<4;r++) acc[i][j][r]=0.f;

    int lr = tid>>1;
    int lc = (tid&1)*2;

    for (int k0=0; k0<Ff; k0+=KT){
        const uint4* asrc_h = (const uint4*)(g_xh + (size_t)(m0+lr)*Ff + k0);
        const uint4* asrc_l = (const uint4*)(g_xl + (size_t)(m0+lr)*Ff + k0);
        const uint4* bsrc_h = (const uint4*)(WhT  + (size_t)lr*Ff + k0);
        const uint4* bsrc_l = (const uint4*)(WlT  + (size_t)lr*Ff + k0);
        uint4* adst_h = (uint4*)(Ah + lr*SSTR);
        uint4* adst_l = (uint4*)(Al + lr*SSTR);
        uint4* bdst_h = (uint4*)(Bh + lr*SSTR);
        uint4* bdst_l = (uint4*)(Bl + lr*SSTR);
        #pragma unroll
        for (int c=0;c<2;c++){
            adst_h[lc+c] = asrc_h[lc+c];
            adst_l[lc+c] = asrc_l[lc+c];
            bdst_h[lc+c] = bsrc_h[lc+c];
            bdst_l[lc+c] = bsrc_l[lc+c];
        }
        __syncthreads();

        const uint32_t* AhU = (const uint32_t*)Ah;
        const uint32_t* AlU = (const uint32_t*)Al;
        const uint32_t* BhU = (const uint32_t*)Bh;
        const uint32_t* BlU = (const uint32_t*)Bl;
        #pragma unroll
        for (int kk=0; kk<KT/2; kk+=8){
            uint32_t ahf[4][4], alf[4][4], bhf[4][2], blf[4][2];
            #pragma unroll
            for (int i=0;i<4;i++){
                int rb = (wm*64 + i*16 + g)*(SSTR/2) + kk + tig;
                ahf[i][0] = AhU[rb];
                ahf[i][1] = AhU[rb + 8*(SSTR/2)];
                ahf[i][2] = AhU[rb + 4];
                ahf[i][3] = AhU[rb + 8*(SSTR/2) + 4];
                alf[i][0] = AlU[rb];
                alf[i][1] = AlU[rb + 8*(SSTR/2)];
                alf[i][2] = AlU[rb + 4];
                alf[i][3] = AlU[rb + 8*(SSTR/2) + 4];
            }
            #pragma unroll
            for (int j=0;j<4;j++){
                int rb = (wn*32 + j*8 + g)*(SSTR/2) + kk + tig;
                bhf[j][0] = BhU[rb];
                bhf[j][1] = BhU[rb + 4];
                blf[j][0] = BlU[rb];
                blf[j][1] = BlU[rb + 4];
            }
            #pragma unroll
            for (int i=0;i<4;i++)
                #pragma unroll
                for (int j=0;j<4;j++)
                    mma16816(acc[i][j], ahf[i], bhf[j]);
            #pragma unroll
            for (int i=0;i<4;i++)
                #pragma unroll
                for (int j=0;j<4;j++)
                    mma16816(acc[i][j], ahf[i], blf[j]);
            #pragma unroll
            for (int i=0;i<4;i++)
                #pragma unroll
                for (int j=0;j<4;j++)
                    mma16816(acc[i][j], alf[i], bhf[j]);
        }
        __syncthreads();
    }

    #pragma unroll
    for (int i=0;i<4;i++){
        #pragma unroll
        for (int j=0;j<4;j++){
            int m = m0 + wm*64 + i*16 + g;
            int n = wn*32 + j*8 + 2*tig;
            float v[4];
            #pragma unroll
            for (int r=0;r<4;r++) v[r] = acc[i][j][r];
            if (mid<=1){
                #pragma unroll
                for (int r=0;r<4;r++) v[r] = (v[r]>0.f) ? v[r]+1.f : expf(v[r]);
            } else if (mid==3){
                v[0] += __ldg(&scb[n]);   v[1] += __ldg(&scb[n+1]);
                v[2] += __ldg(&scb[n]);   v[3] += __ldg(&scb[n+1]);
            }
            *(float2*)&outp[(size_t)m*Dd + n]     = make_float2(v[0], v[1]);
            *(float2*)&outp[(size_t)(m+8)*Dd + n] = make_float2(v[2], v[3]);
        }
    }
}

// ---------------- shared tile loaders (256-thread blocks) -----------------
__device__ __forceinline__ void loadA(float* As, const float* __restrict__ src,
                                      int d0, int stride){
    int tid = threadIdx.x;
    int r = tid/8, c4 = (tid%8)*4;
    #pragma unroll
    for (int rr=0; rr<128; rr+=32){
        float4 v = *(const float4*)&src[(size_t)(rr+r)*stride + d0 + c4];
        As[(rr+r)*33 + c4+0] = v.x;
        As[(rr+r)*33 + c4+1] = v.y;
        As[(rr+r)*33 + c4+2] = v.z;
        As[(rr+r)*33 + c4+3] = v.w;
    }
}
__device__ __forceinline__ void loadAT(float* dst, const float* __restrict__ src,
                                       int d0, int stride){
    int tid = threadIdx.x;
    int r = tid/8, c4 = (tid%8)*4;
    #pragma unroll
    for (int rr=0; rr<128; rr+=32){
        float4 v = *(const float4*)&src[(size_t)(rr+r)*stride + d0 + c4];
        dst[(c4+0)*128 + rr+r] = v.x;
        dst[(c4+1)*128 + rr+r] = v.y;
        dst[(c4+2)*128 + rr+r] = v.z;
        dst[(c4+3)*128 + rr+r] = v.w;
    }
}
__device__ __forceinline__ void loadB(float* Bs, const float* __restrict__ src,
                                      int stride){
    int tid = threadIdx.x;
    int r = tid/32, c4 = (tid%32)*4;
    #pragma unroll
    for (int rr=0; rr<32; rr+=8)
        *(float4*)&Bs[(rr+r)*128 + c4] =
            *(const float4*)&src[(size_t)(rr+r)*stride + c4];
}

// ---------------- K_chunksum : per-SUBCHUNK (32 tok) partial KV sums ------
__global__ __launch_bounds__(256)
void k_chunksum(){
    __shared__ float Ks[32*128];
    __shared__ float Vs[32*128];
    int sb = blockIdx.x;                 // 0..NC*4-1
    int tid = threadIdx.x, tx = tid%16, ty = tid/16;
    size_t base = (size_t)sb * 32 * Dd;  // 32-token subchunk
    float acc[8][8];
    #pragma unroll
    for (int i=0;i<8;i++)
        #pragma unroll
        for (int j=0;j<8;j++) acc[i][j]=0.f;

    loadB(Ks, g_Kb + base, Dd);
    loadB(Vs, g_Vb + base, Dd);
    __syncthreads();
    #pragma unroll
    for (int s=0;s<32;s++){
        float a[8], b[8];
        #pragma unroll
        for (int i=0;i<8;i++) a[i] = Ks[s*128 + ty*8 + i];
        *(float4*)&b[0] = *(float4*)&Vs[s*128 + tx*8];
        *(float4*)&b[4] = *(float4*)&Vs[s*128 + tx*8 + 4];
        #pragma unroll
        for (int i=0;i<8;i++)
            #pragma unroll
            for (int j=0;j<8;j++)
                acc[i][j] = fmaf(a[i], b[j], acc[i][j]);
    }
    size_t ob = (size_t)sb*Dd*Dd;
    #pragma unroll
    for (int i=0;i<8;i++){
        *(float4*)&g_KVp[ob + (size_t)(ty*8+i)*Dd + tx*8]     = *(float4*)&acc[i][0];
        *(float4*)&g_KVp[ob + (size_t)(ty*8+i)*Dd + tx*8 + 4] = *(float4*)&acc[i][4];
    }
}

// ---------------- K_kc : per-chunk sums of K (512 threads) ----------------
__global__ void k_kc(){
    __shared__ float part[4][128];
    int bc = blockIdx.x; int tid = threadIdx.x;
    int ts = tid>>7, d = tid&127;
    size_t base = ((size_t)bc*Lc + ts*32)*Dd + d;
    float a=0.f;
    #pragma unroll
    for (int t=0;t<32;t++) a += g_Kb[base + (size_t)t*Dd];
    part[ts][d] = a;
    __syncthreads();
    if (tid < 128)
        g_Kc[bc*Dd + tid] = (part[0][tid]+part[1][tid])+(part[2][tid]+part[3][tid]);
}

// ---------------- K_prefix : exclusive prefix over chunks (+S0) -----------
__global__ void k_prefix(const float* __restrict__ S0){
    int i = blockIdx.x, b = blockIdx.y, j = threadIdx.x;
    float r = S0[((size_t)b*Dd + i)*Dd + j];
    for (int c=0;c<CC;c++){
        int bc = b*CC + c;
        size_t idx = ((size_t)bc*Dd + i)*Dd + j;
        g_Pex[idx] = r;
        size_t pbase = ((size_t)(bc*4)*Dd + i)*Dd + j;
        float s0 = g_KVp[pbase];
        float s1 = g_KVp[pbase + (size_t)Dd*Dd];
        float s2 = g_KVp[pbase + 2*(size_t)Dd*Dd];
        float s3 = g_KVp[pbase + 3*(size_t)Dd*Dd];
        r += (s0+s1)+(s2+s3);
    }
}

// ---------------- K_zex : exclusive prefix of K chunk sums (+Z0) ----------
__global__ void k_zex(const float* __restrict__ Z0){
    int b = blockIdx.x, d = threadIdx.x;
    float r = Z0[b*Dd + d];
    for (int c=0;c<CC;c++){
        g_Zex[(b*CC+c)*Dd + d] = r;
        r += g_Kc[(b*CC+c)*Dd + d];
    }
}

// ================= fused tail: num+ffn blocks [0,NC) ; scan blocks =========
#define TAIL_SMEM_FLOATS (128*129 + 128*33 + 32*128 + 128 + 128)

__device__ void scan_role(float* sm, int sb,
                          float* __restrict__ Sout, float* __restrict__ Zout){
    // sb in [0, NC*4): chunk = sb>>2, gpair = sb&3, 256 threads = 2 g-groups
    int bc = sb >> 2;
    int gpair = sb & 3;
    int tid = threadIdx.x;
    int half = tid >> 7;          // 0/1 -> g
    int t128 = tid & 127;
    int g = gpair*2 + half;
    int js = t128 & 31;
    int isub = t128 >> 5;
    int ib = g*16 + isub*4;
    size_t tokbase = (size_t)bc * Lc;

    float* sk = sm;               // [2][128*16]
    for (int idx = t128; idx < 128*16; idx += 128){
        int t_ = idx >> 4, i_ = idx & 15;
        sk[half*2048 + idx] = g_Kb[(tokbase + t_)*Dd + g*16 + i_];
    }

    float4 R[4];
    size_t pbase = (size_t)bc*Dd*Dd;
    #pragma unroll
    for (int a=0;a<4;a++)
        R[a] = *(const float4*)&g_Pex[pbase + (size_t)(ib+a)*Dd + js*4];

    bool doZ = (g==0 && isub==0);
    float4 zr = make_float4(0,0,0,0);
    if (doZ) zr = *(const float4*)&g_Zex[(size_t)bc*Dd + js*4];
    __syncthreads();

    size_t srow = tokbase * Dd * Dd;
    const float* skh = sk + half*2048;
    for (int t=0; t<Lc; t++){
        float4 v = *(const float4*)&g_Vb[(tokbase + t)*Dd + js*4];
        size_t so = srow + (size_t)t*Dd*Dd + js*4;
        #pragma unroll
        for (int a=0;a<4;a++){
            float kk = skh[t*16 + isub*4 + a];
            R[a].x = fmaf(kk, v.x, R[a].x);
            R[a].y = fmaf(kk, v.y, R[a].y);
            R[a].z = fmaf(kk, v.z, R[a].z);
            R[a].w = fmaf(kk, v.w, R[a].w);
            float4 w;
            w.x = clipf(R[a].x); w.y = clipf(R[a].y);
            w.z = clipf(R[a].z); w.w = clipf(R[a].w);
            *(float4*)&Sout[so + (size_t)(ib+a)*Dd] = w;
        }
        if (doZ){
            float4 kv = *(const float4*)&g_Kb[(tokbase + t)*Dd + js*4];
            zr.x += kv.x; zr.y += kv.y; zr.z += kv.z; zr.w += kv.w;
            float4 w;
            w.x = clipf(zr.x); w.y = clipf(zr.y);
            w.z = clipf(zr.z); w.w = clipf(zr.w);
            *(float4*)&Zout[(tokbase + t)*Dd + js*4] = w;
        }
    }
}

__device__ void num_ffn_role(float* sm, int bc,
                             const float* __restrict__ w1, const float* __restrict__ b1,
                             const float* __restrict__ w2, const float* __restrict__ b2,
                             float* __restrict__ outp){
    float* xs  = sm;                     // 128*129 (AQK, then o0, then hidden)
    float* As  = xs + 128*129;           // 128*33
    float* Bs  = As + 128*33;            // 32*128
    float* den = Bs + 32*128;            // 128
    float* zs  = den + 128;              // 128

    int tid = threadIdx.x, tx = tid%16, ty = tid/16;
    size_t tok0 = (size_t)bc * Lc;
    size_t pbase = (size_t)bc*Dd*Dd;

    if (tid < 128) zs[tid] = g_Zex[(size_t)bc*Dd + tid];

    float acc[8][8];
    float qzp[8];
    #pragma unroll
    for (int i=0;i<8;i++){ qzp[i]=0.f;
        #pragma unroll
        for (int j=0;j<8;j++) acc[i][j]=0.f; }
    __syncthreads();

    // ---- stage 1: AQK[t][s] = Q_t . K_s ----
    for (int d0=0; d0<Dd; d0+=32){
        loadA (As, g_Qb + tok0*Dd, d0, Dd);
        loadAT(Bs, g_Kb + tok0*Dd, d0, Dd);
        __syncthreads();
        #pragma unroll
        for (int k=0;k<32;k++){
            float a[8], b[8];
            #pragma unroll
            for (int i=0;i<8;i++) a[i] = As[(ty*8+i)*33 + k];
            *(float4*)&b[0] = *(float4*)&Bs[k*128 + tx*8];
            *(float4*)&b[4] = *(float4*)&Bs[k*128 + tx*8 + 4];
            #pragma unroll
            for (int i=0;i<8;i++)
                #pragma unroll
                for (int j=0;j<8;j++)
                    acc[i][j] = fmaf(a[i], b[j], acc[i][j]);
            if (tx==0){
                float zz = zs[d0+k];
                #pragma unroll
                for (int i=0;i<8;i++) qzp[i] = fmaf(a[i], zz, qzp[i]);
            }
        }
        __syncthreads();
    }
    #pragma unroll
    for (int i=0;i<8;i++){
        int t = ty*8+i;
        #pragma unroll
        for (int j=0;j<8;j++){
            int s = tx*8+j;
            xs[t*129 + s] = (s<=t) ? acc[i][j] : 0.f;
        }
    }
    if (tx==0){
        #pragma unroll
        for (int i=0;i<8;i++) den[ty*8+i] = qzp[i];
    }
    __syncthreads();
    if (tid < 128){
        float rs = 0.f;
        #pragma unroll 8
        for (int s=0;s<128;s++) rs += xs[tid*129 + s];
        den[tid] = den[tid] + rs + EPS_DEN;
    }
    __syncthreads();

    // ---- stage 2a: acc = tril(AQK) @ V ----
    #pragma unroll
    for (int i=0;i<8;i++)
        #pragma unroll
        for (int j=0;j<8;j++) acc[i][j]=0.f;

    for (int s0=0; s0<128; s0+=32){
        loadB(Bs, g_Vb + (tok0+s0)*Dd, Dd);
        __syncthreads();
        #pragma unroll
        for (int k=0;k<32;k++){
            int s = s0 + k;
            float a[8], b[8];
            #pragma unroll
            for (int i=0;i<8;i++) a[i] = xs[(ty*8+i)*129 + s];
            *(float4*)&b[0] = *(float4*)&Bs[k*128 + tx*8];
            *(float4*)&b[4] = *(float4*)&Bs[k*128 + tx*8 + 4];
            #pragma unroll
            for (int i=0;i<8;i++)
                #pragma unroll
                for (int j=0;j<8;j++)
                    acc[i][j] = fmaf(a[i], b[j], acc[i][j]);
        }
        __syncthreads();
    }
    // ---- stage 2b: acc += Q @ Pex ----
    for (int d0=0; d0<Dd; d0+=32){
        loadA(As, g_Qb + tok0*Dd, d0, Dd);
        loadB(Bs, g_Pex + pbase + (size_t)d0*Dd, Dd);
        __syncthreads();
        #pragma unroll
        for (int k=0;k<32;k++){
            float a[8], b[8];
            #pragma unroll
            for (int i=0;i<8;i++) a[i] = As[(ty*8+i)*33 + k];
            *(float4*)&b[0] = *(float4*)&Bs[k*128 + tx*8];
            *(float4*)&b[4] = *(float4*)&Bs[k*128 + tx*8 + 4];
            #pragma unroll
            for (int i=0;i<8;i++)
                #pragma unroll
                for (int j=0;j<8;j++)
                    acc[i][j] = fmaf(a[i], b[j], acc[i][j]);
        }
        __syncthreads();
    }
    // ---- o0 = num/den -> xs (smem, no gmem round trip) ----
    #pragma unroll
    for (int i=0;i<8;i++){
        float dd = den[ty*8+i];
        #pragma unroll
        for (int j=0;j<8;j++)
            xs[(ty*8+i)*129 + tx*8+j] = acc[i][j] / dd;
    }
    __syncthreads();

    // ---- ffn stage 1: h = relu(o0 @ w1 + b1) ----
    #pragma unroll
    for (int i=0;i<8;i++)
        #pragma unroll
        for (int j=0;j<8;j++) acc[i][j]=0.f;

    for (int d0=0; d0<Dd; d0+=32){
        loadB(Bs, w1 + (size_t)d0*Dd, Dd);
        __syncthreads();
        #pragma unroll
        for (int k=0;k<32;k++){
            float a[8], b[8];
            #pragma unroll
            for (int i=0;i<8;i++) a[i] = xs[(ty*8+i)*129 + d0 + k];
            *(float4*)&b[0] = *(float4*)&Bs[k*128 + tx*8];
            *(float4*)&b[4] = *(float4*)&Bs[k*128 + tx*8 + 4];
            #pragma unroll
            for (int i=0;i<8;i++)
                #pragma unroll
                for (int j=0;j<8;j++)
                    acc[i][j] = fmaf(a[i], b[j], acc[i][j]);
        }
        __syncthreads();
    }
    #pragma unroll
    for (int i=0;i<8;i++)
        #pragma unroll
        for (int j=0;j<8;j++){
            float h = acc[i][j] + __ldg(&b1[tx*8+j]);
            xs[(ty*8+i)*129 + tx*8+j] = fmaxf(h, 0.f);
        }
    __syncthreads();

    // ---- ffn stage 2: out = relu(h @ w2 + b2) + shortcut ----
    #pragma unroll
    for (int i=0;i<8;i++)
        #pragma unroll
        for (int j=0;j<8;j++) acc[i][j]=0.f;

    for (int d0=0; d0<Dd; d0+=32){
        loadB(Bs, w2 + (size_t)d0*Dd, Dd);
        __syncthreads();
        #pragma unroll
        for (int k=0;k<32;k++){
            float a[8], b[8];
            #pragma unroll
            for (int i=0;i<8;i++) a[i] = xs[(ty*8+i)*129 + d0 + k];
            *(float4*)&b[0] = *(float4*)&Bs[k*128 + tx*8];
            *(float4*)&b[4] = *(float4*)&Bs[k*128 + tx*8 + 4];
            #pragma unroll
            for (int i=0;i<8;i++)
                #pragma unroll
                for (int j=0;j<8;j++)
                    acc[i][j] = fmaf(a[i], b[j], acc[i][j]);
        }
        __syncthreads();
    }
    #pragma unroll
    for (int i=0;i<8;i++){
        size_t t = tok0 + ty*8 + i;
        float o[8];
        #pragma unroll
        for (int j=0;j<8;j++){
            int n = tx*8 + j;
            o[j] = fmaxf(acc[i][j] + __ldg(&b2[n]), 0.f) + g_sh[t*Dd + n];
        }
        *(float4*)&outp[t*Dd + tx*8]     = *(float4*)&o[0];
        *(float4*)&outp[t*Dd + tx*8 + 4] = *(float4*)&o[4];
    }
}

__global__ __launch_bounds__(256, 2)
void k_tail(const float* __restrict__ w1, const float* __restrict__ b1,
            const float* __restrict__ w2, const float* __restrict__ b2,
            float* __restrict__ outp, float* __restrict__ Sout,
            float* __restrict__ Zout){
    extern __shared__ float sm[];
    int bid = blockIdx.x;
    if (bid < NC)
        num_ffn_role(sm, bid, w1, b1, w2, b2, outp);
    else
        scan_role(sm, bid - NC, Sout, Zout);
}

// ---------------- launch ---------------------------------------------------
extern "C" void kernel_launch(void* const* d_in, const int* in_sizes, int n_in,
                              void* d_out, int out_size){
    const float* hist = (const float*)d_in[0];
    const float* S0   = (const float*)d_in[1];
    const float* Z0   = (const float*)d_in[2];
    const float* Wk   = (const float*)d_in[3];
    const float* Wq   = (const float*)d_in[4];
    const float* Wv   = (const float*)d_in[5];
    const float* lng  = (const float*)d_in[6];
    const float* lnb  = (const float*)d_in[7];
    const float* w1   = (const float*)d_in[8];
    const float* b1   = (const float*)d_in[9];
    const float* w2   = (const float*)d_in[10];
    const float* b2   = (const float*)d_in[11];
    const float* scw  = (const float*)d_in[12];
    const float* scb  = (const float*)d_in[13];

    float* out  = (float*)d_out;
    float* Sout = out + (size_t)BT*Dd;
    float* Zout = Sout + (size_t)BT*Dd*Dd;

    long long full = (long long)BT*Dd + (long long)BT*Dd*Dd + (long long)BT*Dd;
    bool writeS = ((long long)out_size >= full);

    cudaFuncSetAttribute(k_tail, cudaFuncAttributeMaxDynamicSharedMemorySize,
                         TAIL_SMEM_FLOATS*4);

    k_ln<<<BT, 128>>>(hist, lng, lnb);
    dim3 gw(Ff/32, Dd/32, 4);
    k_wconv<<<gw, dim3(32,8)>>>(Wk, Wq, Wv, scw);
    dim3 gp(BT/128, 4);
    k_proj<<<gp, 256>>>(scb);
    k_chunksum<<<NC*4, 256>>>();
    k_kc<<<NC, 512>>>();
    dim3 gpx(Dd, Bb);
    k_prefix<<<gpx, 128>>>(S0);
    k_zex<<<Bb, 128>>>(Z0);
    int tailBlocks = writeS ? (NC + NSCAN) : NC;
    k_tail<<<tailBlocks, 256, TAIL_SMEM_FLOATS*4>>>(w1, b1, w2, b2,
                                                    out, Sout, Zout);
}